// round 4
// baseline (speedup 1.0000x reference)
#include <cuda_runtime.h>
#include <cuda_bf16.h>
#include <math.h>

// ---------------------------------------------------------------------------
// MAD_4612794876398  (round 3)
//  K1 lenet_kernel: pack-free FFMA2 convs. Accumulators are spatial pairs
//     (a0,a1)/(a2,a3); inputs are pre-packed overlapping pairs in smem;
//     weights are pre-duplicated (w,w) in smem. Query blocks additionally
//     compute grad = Wg·feat+bg (120) and x = Wf·feat+bf (12); ref blocks
//     compute rx = Wf·feat+bf (12). No 400-float feature ever hits HBM.
//  K2 head_kernel: tiny combine (diff/norm/logits/softmax) on 12-d vectors.
// ---------------------------------------------------------------------------

#define FEAT   400
#define HID    12
#define NCLS   10
#define SMAX   8
#define NQ_MAX 1024
#define NR_MAX (NQ_MAX * SMAX)
#define BDIM   224
#define QPB    4        // head queries per block

__device__ float g_x[NQ_MAX * HID];           // query Wf projections
__device__ float g_grad[NQ_MAX * HID * NCLS]; // query Wg projections
__device__ float g_rx[NR_MAX * HID];          // ref Wf projections

typedef unsigned long long ull;

__device__ __forceinline__ ull pack2(float lo, float hi) {
    ull r; asm("mov.b64 %0, {%1, %2};" : "=l"(r) : "f"(lo), "f"(hi)); return r;
}
__device__ __forceinline__ void unpack2(ull v, float& lo, float& hi) {
    asm("mov.b64 {%0, %1}, %2;" : "=f"(lo), "=f"(hi) : "l"(v));
}
__device__ __forceinline__ ull fma2(ull a, ull b, ull c) {
    ull d; asm("fma.rn.f32x2 %0, %1, %2, %3;" : "=l"(d) : "l"(a), "l"(b), "l"(c));
    return d;
}
__device__ __forceinline__ ull ld64(const float2* p) {
    return *reinterpret_cast<const ull*>(p);
}

// dynamic smem layout (bytes)
//  region A (reused):
//   [0,12288)      s_img   float[3][32][32]        (phase 1 only)
//   [0,8736)       s_p1p   float2[6][14][13]       (after conv1)
//   [8736,10336)   s_feat  float[400]              (conv2 output)
//  [12288,36096)   s_imgp  float2[3][32][31]
//  [36096,39696)   s_wb1   float2[3][25][6]   (w,w)
//  [39696,58896)   s_wb2   float2[6][25][16]  (w,w)
//  [58896,63600)   s_p1    float[6][14][14]
//  [63600,63688)   s_bias  float[22]  (b1[6], b2[16])
#define OFF_FEAT 8736
#define OFF_IMGP 12288
#define OFF_WB1  36096
#define OFF_WB2  39696
#define OFF_P1   58896
#define OFF_BIAS 63600
#define SMEM_TOTAL 63712

__global__ __launch_bounds__(BDIM, 3)
void lenet_kernel(const float* __restrict__ img,
                  const float* __restrict__ train,
                  const int*   __restrict__ refs,
                  const float* __restrict__ w1, const float* __restrict__ b1,
                  const float* __restrict__ w2, const float* __restrict__ b2,
                  const float* __restrict__ Wf, const float* __restrict__ bf,
                  const float* __restrict__ Wg, const float* __restrict__ bg,
                  int n_img)
{
    extern __shared__ char smem_raw[];
    float*  s_img  = (float*) (smem_raw);
    float2* s_p1p  = (float2*)(smem_raw);
    float*  s_feat = (float*) (smem_raw + OFF_FEAT);
    float2* s_imgp = (float2*)(smem_raw + OFF_IMGP);
    float2* s_wb1  = (float2*)(smem_raw + OFF_WB1);
    float2* s_wb2  = (float2*)(smem_raw + OFF_WB2);
    float*  s_p1   = (float*) (smem_raw + OFF_P1);
    float*  s_bias = (float*) (smem_raw + OFF_BIAS);

    const int b = blockIdx.x;
    const int t = threadIdx.x;

    const float* src = (b < n_img)
        ? img + (size_t)b * 3072
        : train + (size_t)refs[b - n_img] * 3072;

    // ---- phase 1: load image + all weights (duplicated pairs) ----
    {
        const float4* s4 = reinterpret_cast<const float4*>(src);
        float4* d4 = reinterpret_cast<float4*>(s_img);
        for (int i = t; i < 768; i += BDIM) d4[i] = s4[i];
    }
    for (int i = t; i < 450; i += BDIM) {        // wb1[ic][k][oc]
        int oc = i % 6, r = i / 6, k = r % 25, ic = r / 25;
        float v = w1[oc * 75 + ic * 25 + k];
        s_wb1[(ic * 25 + k) * 6 + oc] = make_float2(v, v);
    }
    for (int i = t; i < 2400; i += BDIM) {       // wb2[ic][k][oc]
        int oc = i % 16, r = i / 16, k = r % 25, ic = r / 25;
        float v = w2[oc * 150 + ic * 25 + k];
        s_wb2[(ic * 25 + k) * 16 + oc] = make_float2(v, v);
    }
    if (t < 6)  s_bias[t] = b1[t];
    else if (t < 22) s_bias[t] = b2[t - 6];
    __syncthreads();

    // ---- phase 2: build overlapping image pairs ----
    for (int i = t; i < 3 * 32 * 31; i += BDIM) {
        int x = i % 31, r = i / 31, y = r % 32, ic = r / 32;
        const float* row = s_img + (ic * 32 + y) * 32;
        s_imgp[(ic * 32 + y) * 31 + x] = make_float2(row[x], row[x + 1]);
    }
    __syncthreads();

    // ---- conv1 + relu + maxpool2 : 6 x 14 x 14 ----
    if (t < 196) {
        const int py = t / 14, px = t % 14;
        const int iy = 2 * py, ix = 2 * px;

        ull aT[6], aB[6];
        #pragma unroll
        for (int oc = 0; oc < 6; oc++) {
            ull bz = pack2(s_bias[oc], s_bias[oc]);
            aT[oc] = bz; aB[oc] = bz;
        }
        #pragma unroll
        for (int ic = 0; ic < 3; ic++) {
            ull rT[5];
            #pragma unroll
            for (int x = 0; x < 5; x++)
                rT[x] = ld64(&s_imgp[(ic * 32 + iy) * 31 + ix + x]);
            #pragma unroll
            for (int ky = 0; ky < 5; ky++) {
                ull rB[5];
                #pragma unroll
                for (int x = 0; x < 5; x++)
                    rB[x] = ld64(&s_imgp[(ic * 32 + iy + ky + 1) * 31 + ix + x]);
                #pragma unroll
                for (int kx = 0; kx < 5; kx++) {
                    #pragma unroll
                    for (int oc = 0; oc < 6; oc++) {
                        ull w = ld64(&s_wb1[(ic * 25 + ky * 5 + kx) * 6 + oc]);
                        aT[oc] = fma2(w, rT[kx], aT[oc]);
                        aB[oc] = fma2(w, rB[kx], aB[oc]);
                    }
                }
                #pragma unroll
                for (int x = 0; x < 5; x++) rT[x] = rB[x];
            }
        }
        #pragma unroll
        for (int oc = 0; oc < 6; oc++) {
            float a0, a1, a2, a3;
            unpack2(aT[oc], a0, a1);
            unpack2(aB[oc], a2, a3);
            float m = fmaxf(fmaxf(a0, a1), fmaxf(a2, a3));
            s_p1[(oc * 14 + py) * 14 + px] = fmaxf(m, 0.0f);
        }
    }
    __syncthreads();

    // ---- build overlapping p1 pairs (region A reuse; s_img is dead) ----
    for (int i = t; i < 6 * 14 * 13; i += BDIM) {
        int x = i % 13, r = i / 13, y = r % 14, ic = r / 14;
        const float* row = s_p1 + (ic * 14 + y) * 14;
        s_p1p[(ic * 14 + y) * 13 + x] = make_float2(row[x], row[x + 1]);
    }
    __syncthreads();

    // ---- conv2 + relu + maxpool2 : 16 x 5 x 5 = 400 ----
    if (t < 200) {
        const int pos = t >> 3;          // 0..24
        const int j   = t & 7;           // oc pair -> ocs 2j, 2j+1
        const int py = pos / 5, px = pos % 5;
        const int iy = 2 * py, ix = 2 * px;

        ull aT0, aB0, aT1, aB1;
        {
            ull z0 = pack2(s_bias[6 + 2*j],     s_bias[6 + 2*j]);
            ull z1 = pack2(s_bias[6 + 2*j + 1], s_bias[6 + 2*j + 1]);
            aT0 = z0; aB0 = z0; aT1 = z1; aB1 = z1;
        }
        #pragma unroll
        for (int ic = 0; ic < 6; ic++) {
            ull rT[5];
            #pragma unroll
            for (int x = 0; x < 5; x++)
                rT[x] = ld64(&s_p1p[(ic * 14 + iy) * 13 + ix + x]);
            #pragma unroll
            for (int ky = 0; ky < 5; ky++) {
                ull rB[5];
                #pragma unroll
                for (int x = 0; x < 5; x++)
                    rB[x] = ld64(&s_p1p[(ic * 14 + iy + ky + 1) * 13 + ix + x]);
                #pragma unroll
                for (int kx = 0; kx < 5; kx++) {
                    const int wi = (ic * 25 + ky * 5 + kx) * 16;
                    ull w0 = ld64(&s_wb2[wi + 2*j]);
                    ull w1v = ld64(&s_wb2[wi + 2*j + 1]);
                    aT0 = fma2(w0,  rT[kx], aT0);
                    aB0 = fma2(w0,  rB[kx], aB0);
                    aT1 = fma2(w1v, rT[kx], aT1);
                    aB1 = fma2(w1v, rB[kx], aB1);
                }
                #pragma unroll
                for (int x = 0; x < 5; x++) rT[x] = rB[x];
            }
        }
        float a0, a1, a2, a3, m;
        unpack2(aT0, a0, a1); unpack2(aB0, a2, a3);
        m = fmaxf(fmaxf(a0, a1), fmaxf(a2, a3));
        s_feat[(2*j) * 25 + pos] = fmaxf(m, 0.0f);
        unpack2(aT1, a0, a1); unpack2(aB1, a2, a3);
        m = fmaxf(fmaxf(a0, a1), fmaxf(a2, a3));
        s_feat[(2*j + 1) * 25 + pos] = fmaxf(m, 0.0f);
    }
    __syncthreads();

    // ---- epilogue: projections (warp-cooperative 400-dots) ----
    const int warp = t >> 5, lane = t & 31;
    const float4* f4 = reinterpret_cast<const float4*>(s_feat);

    if (b < n_img) {
        // query: 120 Wg rows + 12 Wf rows
        for (int d = warp; d < HID * NCLS + HID; d += (BDIM >> 5)) {
            const float* wrow; float bias;
            if (d < HID * NCLS) { wrow = Wg + (size_t)d * FEAT; bias = bg[d]; }
            else { wrow = Wf + (size_t)(d - HID*NCLS) * FEAT; bias = bf[d - HID*NCLS]; }
            const float4* w4 = reinterpret_cast<const float4*>(wrow);
            float acc = 0.0f;
            #pragma unroll
            for (int it = 0; it < 4; it++) {
                int e = lane + it * 32;
                if (e < 100) {
                    float4 a = f4[e], w = w4[e];
                    acc += a.x*w.x + a.y*w.y + a.z*w.z + a.w*w.w;
                }
            }
            #pragma unroll
            for (int o = 16; o > 0; o >>= 1)
                acc += __shfl_xor_sync(0xFFFFFFFFu, acc, o);
            if (lane == 0) {
                float v = acc + bias;
                if (d < HID * NCLS) g_grad[(size_t)b * (HID*NCLS) + d] = v;
                else                g_x[(size_t)b * HID + (d - HID*NCLS)] = v;
            }
        }
    } else {
        // ref: 12 Wf rows
        const int slot = b - n_img;
        for (int d = warp; d < HID; d += (BDIM >> 5)) {
            const float4* w4 = reinterpret_cast<const float4*>(Wf + (size_t)d * FEAT);
            float acc = 0.0f;
            #pragma unroll
            for (int it = 0; it < 4; it++) {
                int e = lane + it * 32;
                if (e < 100) {
                    float4 a = f4[e], w = w4[e];
                    acc += a.x*w.x + a.y*w.y + a.z*w.z + a.w*w.w;
                }
            }
            #pragma unroll
            for (int o = 16; o > 0; o >>= 1)
                acc += __shfl_xor_sync(0xFFFFFFFFu, acc, o);
            if (lane == 0) g_rx[(size_t)slot * HID + d] = acc + bf[d];
        }
    }
}

// ---------------------------------------------------------------------------
// Head kernel: QPB queries per block, 128 threads. Tiny combine.
// ---------------------------------------------------------------------------
__global__ __launch_bounds__(128)
void head_kernel(const float* __restrict__ mem,
                 const int*   __restrict__ refs,
                 const float* __restrict__ Wm, const float* __restrict__ bm,
                 float* __restrict__ out, int n, int S)
{
    __shared__ float s_x[QPB][HID];
    __shared__ float s_g[QPB][HID * NCLS];
    __shared__ float s_diff[QPB][SMAX][HID];
    __shared__ float s_norm[QPB][SMAX];
    __shared__ float s_mem[QPB][SMAX][NCLS];
    __shared__ float s_logit[QPB][SMAX][NCLS];
    __shared__ float s_wm[NCLS * NCLS];
    __shared__ float s_bm[NCLS];
    __shared__ int   s_refs[QPB][SMAX];

    const int t = threadIdx.x;
    const int q0 = blockIdx.x * QPB;

    if (t < QPB * SMAX) {
        int ql = t / SMAX, s = t % SMAX;
        s_refs[ql][s] = refs[(size_t)(q0 + ql) * S + s];
    }
    if (t < QPB * HID) {
        int ql = t / HID, h = t % HID;
        s_x[ql][h] = g_x[(size_t)(q0 + ql) * HID + h];
    }
    for (int i = t; i < QPB * HID * NCLS; i += 128) {
        int ql = i / (HID * NCLS), d = i % (HID * NCLS);
        s_g[ql][d] = g_grad[(size_t)(q0 + ql) * (HID*NCLS) + d];
    }
    if (t < NCLS * NCLS) s_wm[t] = Wm[t];
    if (t < NCLS) s_bm[t] = bm[t];
    __syncthreads();

    // mem gather
    for (int i = t; i < QPB * SMAX * NCLS; i += 128) {
        int ql = i / (SMAX * NCLS), r2 = i % (SMAX * NCLS);
        int s = r2 / NCLS, c = r2 % NCLS;
        s_mem[ql][s][c] = mem[(size_t)s_refs[ql][s] * NCLS + c];
    }
    // diff + norm
    if (t < QPB * SMAX) {
        int ql = t / SMAX, s = t % SMAX;
        float acc = 0.0f;
        #pragma unroll
        for (int h = 0; h < HID; h++) {
            float rx = g_rx[(size_t)((q0 + ql) * S + s) * HID + h];
            float dd = s_x[ql][h] - rx;
            s_diff[ql][s][h] = dd;
            acc += dd * dd;
        }
        s_norm[ql][s] = sqrtf(acc);
    }
    __syncthreads();

    // logits
    for (int i = t; i < QPB * SMAX * NCLS; i += 128) {
        int ql = i / (SMAX * NCLS), r2 = i % (SMAX * NCLS);
        int s = r2 / NCLS, c = r2 % NCLS;
        float acc = s_bm[c];
        #pragma unroll
        for (int jj = 0; jj < NCLS; jj++)
            acc += s_wm[c * NCLS + jj] * s_mem[ql][s][jj];
        #pragma unroll
        for (int h = 0; h < HID; h++)
            acc += s_diff[ql][s][h] * s_g[ql][h * NCLS + c];
        s_logit[ql][s][c] = acc;
    }
    __syncthreads();

    // softmax(-norm) weighted combine
    if (t < QPB * NCLS) {
        int ql = t / NCLS, c = t % NCLS;
        float mx = -1e30f;
        for (int s = 0; s < S; s++) mx = fmaxf(mx, -s_norm[ql][s]);
        float se = 0.0f, acc = 0.0f;
        for (int s = 0; s < S; s++) {
            float e = expf(-s_norm[ql][s] - mx);
            se += e;
            acc += e * s_logit[ql][s][c];
        }
        out[(size_t)(q0 + ql) * NCLS + c] = acc / se;
    }
}

// ---------------------------------------------------------------------------
// launcher
// ---------------------------------------------------------------------------
extern "C" void kernel_launch(void* const* d_in, const int* in_sizes, int n_in,
                              void* d_out, int out_size)
{
    const float* img   = (const float*)d_in[0];
    const float* train = (const float*)d_in[1];
    const float* mem   = (const float*)d_in[2];
    const float* w1    = (const float*)d_in[3];
    const float* b1    = (const float*)d_in[4];
    const float* w2    = (const float*)d_in[5];
    const float* b2    = (const float*)d_in[6];
    const float* Wf    = (const float*)d_in[7];
    const float* bf    = (const float*)d_in[8];
    const float* Wg    = (const float*)d_in[9];
    const float* bg    = (const float*)d_in[10];
    const float* Wm    = (const float*)d_in[11];
    const float* bm    = (const float*)d_in[12];
    // d_in[13] = idx : unused by the reference computation
    const int*   refs  = (const int*)d_in[14];

    const int n = in_sizes[0] / (3 * 32 * 32);   // 1024
    const int S = in_sizes[14] / n;              // 8
    if (n > NQ_MAX || S != SMAX || (n % QPB) != 0) return;

    cudaFuncSetAttribute(lenet_kernel,
                         cudaFuncAttributeMaxDynamicSharedMemorySize, SMEM_TOTAL);

    const int ntot = n + n * S;                  // 9216
    lenet_kernel<<<ntot, BDIM, SMEM_TOTAL>>>(img, train, refs,
                                             w1, b1, w2, b2,
                                             Wf, bf, Wg, bg, n);
    head_kernel<<<n / QPB, 128>>>(mem, refs, Wm, bm, (float*)d_out, n, S);
}

// round 5
// speedup vs baseline: 1.3019x; 1.3019x over previous
#include <cuda_runtime.h>
#include <cuda_bf16.h>
#include <math.h>

// ---------------------------------------------------------------------------
// MAD_4612794876398  (round 4)
//  Dual-image FFMA2: each lenet block processes TWO images; every smem value
//  is a 64-bit (imgA, imgB) pair, so each fma.rn.f32x2 does one conv MAC for
//  two images with zero pack MOVs and R2-level smem traffic per image.
//  Epilogue (fused): query blocks compute grad=Wg·feat+bg and x=Wf·feat+bf,
//  ref blocks compute rx=Wf·feat+bf. Head kernel does the tiny combine.
// ---------------------------------------------------------------------------

#define FEAT   400
#define HID    12
#define NCLS   10
#define SMAX   8
#define NQ_MAX 1024
#define NR_MAX (NQ_MAX * SMAX)
#define BDIM   224
#define QPB    4

__device__ float g_x[NQ_MAX * HID];
__device__ float g_grad[NQ_MAX * HID * NCLS];
__device__ float g_rx[NR_MAX * HID];

typedef unsigned long long ull;

__device__ __forceinline__ ull pack2(float lo, float hi) {
    ull r; asm("mov.b64 %0, {%1, %2};" : "=l"(r) : "f"(lo), "f"(hi)); return r;
}
__device__ __forceinline__ void unpack2(ull v, float& lo, float& hi) {
    asm("mov.b64 {%0, %1}, %2;" : "=f"(lo), "=f"(hi) : "l"(v));
}
__device__ __forceinline__ ull fma2(ull a, ull b, ull c) {
    ull d; asm("fma.rn.f32x2 %0, %1, %2, %3;" : "=l"(d) : "l"(a), "l"(b), "l"(c));
    return d;
}

// dynamic smem layout (bytes), all regions ull (16B-friendly):
//  [0,24576)        s_img2  ull[3*32*32]       (A,B) image pairs
//  [24576,28192)    s_wb1   ull[3*25*6]        (w,w)
//  [28192,47392)    s_wb2   ull[6*25*16]       (w,w)
//  [47392,56800)    s_p12   ull[6*14*14]       pooled pairs
//  [56800,60000)    s_feat2 ull[400]           feature pairs
//  [60000,60176)    s_bias2 ull[22]            (b,b)
#define OFF_WB1  24576
#define OFF_WB2  28192
#define OFF_P1   47392
#define OFF_FEAT 56800
#define OFF_BIAS 60000
#define SMEM_TOTAL 60192

__global__ __launch_bounds__(BDIM, 2)
void lenet_kernel(const float* __restrict__ img,
                  const float* __restrict__ train,
                  const int*   __restrict__ refs,
                  const float* __restrict__ w1, const float* __restrict__ b1,
                  const float* __restrict__ w2, const float* __restrict__ b2,
                  const float* __restrict__ Wf, const float* __restrict__ bf,
                  const float* __restrict__ Wg, const float* __restrict__ bg,
                  int n_img)
{
    extern __shared__ char smem_raw[];
    ull* s_img2  = (ull*)(smem_raw);
    ull* s_wb1   = (ull*)(smem_raw + OFF_WB1);
    ull* s_wb2   = (ull*)(smem_raw + OFF_WB2);
    ull* s_p12   = (ull*)(smem_raw + OFF_P1);
    ull* s_feat2 = (ull*)(smem_raw + OFF_FEAT);
    ull* s_bias2 = (ull*)(smem_raw + OFF_BIAS);

    const int b = blockIdx.x;
    const int t = threadIdx.x;
    const int nq2 = n_img >> 1;          // query-pair blocks

    // source pointers for the two images of this block
    const float* srcA;
    const float* srcB;
    if (b < nq2) {
        srcA = img + (size_t)(2 * b) * 3072;
        srcB = img + (size_t)(2 * b + 1) * 3072;
    } else {
        int sA = 2 * (b - nq2);
        srcA = train + (size_t)refs[sA] * 3072;
        srcB = train + (size_t)refs[sA + 1] * 3072;
    }

    // ---- load interleaved image pairs + duplicated weights ----
    {
        const float4* a4 = reinterpret_cast<const float4*>(srcA);
        const float4* b4 = reinterpret_cast<const float4*>(srcB);
        for (int i = t; i < 768; i += BDIM) {
            float4 va = a4[i], vb = b4[i];
            ull* d = s_img2 + 4 * i;
            d[0] = pack2(va.x, vb.x);
            d[1] = pack2(va.y, vb.y);
            d[2] = pack2(va.z, vb.z);
            d[3] = pack2(va.w, vb.w);
        }
    }
    for (int i = t; i < 450; i += BDIM) {          // wb1[(ic*25+k)*6+oc]
        int oc = i % 6, r = i / 6, k = r % 25, ic = r / 25;
        float v = w1[oc * 75 + ic * 25 + k];
        s_wb1[(ic * 25 + k) * 6 + oc] = pack2(v, v);
    }
    for (int i = t; i < 2400; i += BDIM) {         // wb2[(ic*25+k)*16+oc]
        int oc = i % 16, r = i / 16, k = r % 25, ic = r / 25;
        float v = w2[oc * 150 + ic * 25 + k];
        s_wb2[(ic * 25 + k) * 16 + oc] = pack2(v, v);
    }
    if (t < 6)       s_bias2[t] = pack2(b1[t], b1[t]);
    else if (t < 22) s_bias2[t] = pack2(b2[t - 6], b2[t - 6]);
    __syncthreads();

    // ---- conv1 + relu + maxpool2 : 6 x 14 x 14 pairs ----
    if (t < 196) {
        const int py = t / 14, px = t % 14;
        const int iy = 2 * py, ix = 2 * px;

        ull a0[6], a1[6], a2[6], a3[6];
        #pragma unroll
        for (int oc = 0; oc < 6; oc++) {
            ull bz = s_bias2[oc];
            a0[oc] = bz; a1[oc] = bz; a2[oc] = bz; a3[oc] = bz;
        }
        #pragma unroll
        for (int ic = 0; ic < 3; ic++) {
            const ull* base = s_img2 + ic * 1024;
            ull rT[6], rB[6];
            #pragma unroll
            for (int x = 0; x < 6; x++) rT[x] = base[iy * 32 + ix + x];
            #pragma unroll
            for (int ky = 0; ky < 5; ky++) {
                #pragma unroll
                for (int x = 0; x < 6; x++)
                    rB[x] = base[(iy + ky + 1) * 32 + ix + x];
                #pragma unroll
                for (int kx = 0; kx < 5; kx++) {
                    const ull* wrow = s_wb1 + (ic * 25 + ky * 5 + kx) * 6;
                    #pragma unroll
                    for (int oc = 0; oc < 6; oc++) {
                        ull w = wrow[oc];
                        a0[oc] = fma2(w, rT[kx],     a0[oc]);
                        a1[oc] = fma2(w, rT[kx + 1], a1[oc]);
                        a2[oc] = fma2(w, rB[kx],     a2[oc]);
                        a3[oc] = fma2(w, rB[kx + 1], a3[oc]);
                    }
                }
                #pragma unroll
                for (int x = 0; x < 6; x++) rT[x] = rB[x];
            }
        }
        #pragma unroll
        for (int oc = 0; oc < 6; oc++) {
            float p0, p1, q0, q1, r0, r1, s0, s1;
            unpack2(a0[oc], p0, p1);
            unpack2(a1[oc], q0, q1);
            unpack2(a2[oc], r0, r1);
            unpack2(a3[oc], s0, s1);
            float mA = fmaxf(fmaxf(p0, q0), fmaxf(r0, s0));
            float mB = fmaxf(fmaxf(p1, q1), fmaxf(r1, s1));
            s_p12[(oc * 14 + py) * 14 + px] =
                pack2(fmaxf(mA, 0.0f), fmaxf(mB, 0.0f));
        }
    }
    __syncthreads();

    // ---- conv2 + relu + maxpool2 : 16 x 5 x 5 pairs (task = pos, oc-pair) ----
    if (t < 200) {
        const int j   = t / 25;          // oc pair: ocs 2j, 2j+1
        const int pos = t % 25;
        const int py = pos / 5, px = pos % 5;
        const int iy = 2 * py, ix = 2 * px;
        const int oc0 = 2 * j, oc1 = 2 * j + 1;

        ull aA0, aA1, aA2, aA3, aB0, aB1, aB2, aB3;
        {
            ull z0 = s_bias2[6 + oc0], z1 = s_bias2[6 + oc1];
            aA0 = z0; aA1 = z0; aA2 = z0; aA3 = z0;
            aB0 = z1; aB1 = z1; aB2 = z1; aB3 = z1;
        }
        #pragma unroll
        for (int ic = 0; ic < 6; ic++) {
            const ull* base = s_p12 + ic * 196;
            ull rT[6], rB[6];
            #pragma unroll
            for (int x = 0; x < 6; x++) rT[x] = base[iy * 14 + ix + x];
            #pragma unroll
            for (int ky = 0; ky < 5; ky++) {
                #pragma unroll
                for (int x = 0; x < 6; x++)
                    rB[x] = base[(iy + ky + 1) * 14 + ix + x];
                #pragma unroll
                for (int kx = 0; kx < 5; kx++) {
                    const ull* wrow = s_wb2 + (ic * 25 + ky * 5 + kx) * 16;
                    ull w0 = wrow[oc0];
                    ull w1v = wrow[oc1];
                    aA0 = fma2(w0,  rT[kx],     aA0);
                    aA1 = fma2(w0,  rT[kx + 1], aA1);
                    aA2 = fma2(w0,  rB[kx],     aA2);
                    aA3 = fma2(w0,  rB[kx + 1], aA3);
                    aB0 = fma2(w1v, rT[kx],     aB0);
                    aB1 = fma2(w1v, rT[kx + 1], aB1);
                    aB2 = fma2(w1v, rB[kx],     aB2);
                    aB3 = fma2(w1v, rB[kx + 1], aB3);
                }
                #pragma unroll
                for (int x = 0; x < 6; x++) rT[x] = rB[x];
            }
        }
        float p0, p1, q0, q1, r0, r1, s0, s1, mA, mB;
        unpack2(aA0, p0, p1); unpack2(aA1, q0, q1);
        unpack2(aA2, r0, r1); unpack2(aA3, s0, s1);
        mA = fmaxf(fmaxf(p0, q0), fmaxf(r0, s0));
        mB = fmaxf(fmaxf(p1, q1), fmaxf(r1, s1));
        s_feat2[oc0 * 25 + pos] = pack2(fmaxf(mA, 0.0f), fmaxf(mB, 0.0f));
        unpack2(aB0, p0, p1); unpack2(aB1, q0, q1);
        unpack2(aB2, r0, r1); unpack2(aB3, s0, s1);
        mA = fmaxf(fmaxf(p0, q0), fmaxf(r0, s0));
        mB = fmaxf(fmaxf(p1, q1), fmaxf(r1, s1));
        s_feat2[oc1 * 25 + pos] = pack2(fmaxf(mA, 0.0f), fmaxf(mB, 0.0f));
    }
    __syncthreads();

    // ---- epilogue: warp-cooperative 400-dots on feature pairs ----
    const int warp = t >> 5, lane = t & 31;
    const int nrows = (b < nq2) ? (HID * NCLS + HID) : HID;

    for (int d = warp; d < nrows; d += (BDIM >> 5)) {
        const float* wrow; float bias;
        if (b < nq2 && d < HID * NCLS) { wrow = Wg + (size_t)d * FEAT; bias = bg[d]; }
        else {
            int h = (b < nq2) ? (d - HID * NCLS) : d;
            wrow = Wf + (size_t)h * FEAT; bias = bf[h];
        }
        const float4* w4 = reinterpret_cast<const float4*>(wrow);
        ull acc = 0;
        #pragma unroll
        for (int it = 0; it < 4; it++) {
            int e4 = lane + it * 32;
            if (e4 < 100) {
                float4 w = w4[e4];
                const ull* f = s_feat2 + 4 * e4;
                acc = fma2(f[0], pack2(w.x, w.x), acc);
                acc = fma2(f[1], pack2(w.y, w.y), acc);
                acc = fma2(f[2], pack2(w.z, w.z), acc);
                acc = fma2(f[3], pack2(w.w, w.w), acc);
            }
        }
        float sA, sB;
        unpack2(acc, sA, sB);
        #pragma unroll
        for (int o = 16; o > 0; o >>= 1) {
            sA += __shfl_xor_sync(0xFFFFFFFFu, sA, o);
            sB += __shfl_xor_sync(0xFFFFFFFFu, sB, o);
        }
        if (lane == 0) {
            float vA = sA + bias, vB = sB + bias;
            if (b < nq2) {
                int qA = 2 * b, qB = 2 * b + 1;
                if (d < HID * NCLS) {
                    g_grad[(size_t)qA * (HID * NCLS) + d] = vA;
                    g_grad[(size_t)qB * (HID * NCLS) + d] = vB;
                } else {
                    g_x[(size_t)qA * HID + (d - HID * NCLS)] = vA;
                    g_x[(size_t)qB * HID + (d - HID * NCLS)] = vB;
                }
            } else {
                int sA_ = 2 * (b - nq2);
                g_rx[(size_t)sA_ * HID + d]       = vA;
                g_rx[(size_t)(sA_ + 1) * HID + d] = vB;
            }
        }
    }
}

// ---------------------------------------------------------------------------
// Head kernel: tiny combine (unchanged from round 3)
// ---------------------------------------------------------------------------
__global__ __launch_bounds__(128)
void head_kernel(const float* __restrict__ mem,
                 const int*   __restrict__ refs,
                 const float* __restrict__ Wm, const float* __restrict__ bm,
                 float* __restrict__ out, int n, int S)
{
    __shared__ float s_x[QPB][HID];
    __shared__ float s_g[QPB][HID * NCLS];
    __shared__ float s_diff[QPB][SMAX][HID];
    __shared__ float s_norm[QPB][SMAX];
    __shared__ float s_mem[QPB][SMAX][NCLS];
    __shared__ float s_logit[QPB][SMAX][NCLS];
    __shared__ float s_wm[NCLS * NCLS];
    __shared__ float s_bm[NCLS];
    __shared__ int   s_refs[QPB][SMAX];

    const int t = threadIdx.x;
    const int q0 = blockIdx.x * QPB;

    if (t < QPB * SMAX) {
        int ql = t / SMAX, s = t % SMAX;
        s_refs[ql][s] = refs[(size_t)(q0 + ql) * S + s];
    }
    if (t < QPB * HID) {
        int ql = t / HID, h = t % HID;
        s_x[ql][h] = g_x[(size_t)(q0 + ql) * HID + h];
    }
    for (int i = t; i < QPB * HID * NCLS; i += 128) {
        int ql = i / (HID * NCLS), d = i % (HID * NCLS);
        s_g[ql][d] = g_grad[(size_t)(q0 + ql) * (HID * NCLS) + d];
    }
    if (t < NCLS * NCLS) s_wm[t] = Wm[t];
    if (t < NCLS) s_bm[t] = bm[t];
    __syncthreads();

    for (int i = t; i < QPB * SMAX * NCLS; i += 128) {
        int ql = i / (SMAX * NCLS), r2 = i % (SMAX * NCLS);
        int s = r2 / NCLS, c = r2 % NCLS;
        s_mem[ql][s][c] = mem[(size_t)s_refs[ql][s] * NCLS + c];
    }
    if (t < QPB * SMAX) {
        int ql = t / SMAX, s = t % SMAX;
        float acc = 0.0f;
        #pragma unroll
        for (int h = 0; h < HID; h++) {
            float rx = g_rx[(size_t)((q0 + ql) * S + s) * HID + h];
            float dd = s_x[ql][h] - rx;
            s_diff[ql][s][h] = dd;
            acc += dd * dd;
        }
        s_norm[ql][s] = sqrtf(acc);
    }
    __syncthreads();

    for (int i = t; i < QPB * SMAX * NCLS; i += 128) {
        int ql = i / (SMAX * NCLS), r2 = i % (SMAX * NCLS);
        int s = r2 / NCLS, c = r2 % NCLS;
        float acc = s_bm[c];
        #pragma unroll
        for (int jj = 0; jj < NCLS; jj++)
            acc += s_wm[c * NCLS + jj] * s_mem[ql][s][jj];
        #pragma unroll
        for (int h = 0; h < HID; h++)
            acc += s_diff[ql][s][h] * s_g[ql][h * NCLS + c];
        s_logit[ql][s][c] = acc;
    }
    __syncthreads();

    if (t < QPB * NCLS) {
        int ql = t / NCLS, c = t % NCLS;
        float mx = -1e30f;
        for (int s = 0; s < S; s++) mx = fmaxf(mx, -s_norm[ql][s]);
        float se = 0.0f, acc = 0.0f;
        for (int s = 0; s < S; s++) {
            float e = expf(-s_norm[ql][s] - mx);
            se += e;
            acc += e * s_logit[ql][s][c];
        }
        out[(size_t)(q0 + ql) * NCLS + c] = acc / se;
    }
}

// ---------------------------------------------------------------------------
// launcher
// ---------------------------------------------------------------------------
extern "C" void kernel_launch(void* const* d_in, const int* in_sizes, int n_in,
                              void* d_out, int out_size)
{
    const float* img   = (const float*)d_in[0];
    const float* train = (const float*)d_in[1];
    const float* mem   = (const float*)d_in[2];
    const float* w1    = (const float*)d_in[3];
    const float* b1    = (const float*)d_in[4];
    const float* w2    = (const float*)d_in[5];
    const float* b2    = (const float*)d_in[6];
    const float* Wf    = (const float*)d_in[7];
    const float* bf    = (const float*)d_in[8];
    const float* Wg    = (const float*)d_in[9];
    const float* bg    = (const float*)d_in[10];
    const float* Wm    = (const float*)d_in[11];
    const float* bm    = (const float*)d_in[12];
    // d_in[13] = idx : unused
    const int*   refs  = (const int*)d_in[14];

    const int n = in_sizes[0] / (3 * 32 * 32);   // 1024
    const int S = in_sizes[14] / n;              // 8
    if (n > NQ_MAX || S != SMAX || (n % QPB) != 0 || (n % 2) != 0) return;

    cudaFuncSetAttribute(lenet_kernel,
                         cudaFuncAttributeMaxDynamicSharedMemorySize, SMEM_TOTAL);

    const int nblocks = (n + n * S) / 2;         // 4608 image-pair blocks
    lenet_kernel<<<nblocks, BDIM, SMEM_TOTAL>>>(img, train, refs,
                                                w1, b1, w2, b2,
                                                Wf, bf, Wg, bg, n);
    head_kernel<<<n / QPB, 128>>>(mem, refs, Wm, bm, (float*)d_out, n, S);
}

// round 6
// speedup vs baseline: 1.3869x; 1.0653x over previous
#include <cuda_runtime.h>
#include <cuda_bf16.h>
#include <math.h>

// ---------------------------------------------------------------------------
// MAD_4612794876398  (round 5)
//  Dual-image FFMA2 lenet with PARITY-SPLIT smem layouts so every input LDS
//  is lane-stride-1 (conflict-free, 2 wf) and every weight LDS is a broadcast
//  or aligned LDS.128. Crossbar drops below the FFMA2-pipe floor.
//  Epilogue fused (grad/x for queries, rx for refs). Tiny head kernel.
// ---------------------------------------------------------------------------

#define FEAT   400
#define HID    12
#define NCLS   10
#define SMAX   8
#define NQ_MAX 1024
#define NR_MAX (NQ_MAX * SMAX)
#define BDIM   224
#define QPB    4

__device__ float g_x[NQ_MAX * HID];
__device__ float g_grad[NQ_MAX * HID * NCLS];
__device__ float g_rx[NR_MAX * HID];

typedef unsigned long long ull;

__device__ __forceinline__ ull pack2(float lo, float hi) {
    ull r; asm("mov.b64 %0, {%1, %2};" : "=l"(r) : "f"(lo), "f"(hi)); return r;
}
__device__ __forceinline__ void unpack2(ull v, float& lo, float& hi) {
    asm("mov.b64 {%0, %1}, %2;" : "=f"(lo), "=f"(hi) : "l"(v));
}
__device__ __forceinline__ ull fma2(ull a, ull b, ull c) {
    ull d; asm("fma.rn.f32x2 %0, %1, %2, %3;" : "=l"(d) : "l"(a), "l"(b), "l"(c));
    return d;
}

// dynamic smem layout (bytes):
//  [0,24576)        s_img2  ull[3*32*32]   parity-split cols: idx = par*16 + c/2
//  [24576,28192)    s_wb1   ull[3*25*6]    (w,w) dup, [(ic*25+k)*6+oc]
//  [28192,47392)    s_wb2   ull[6*25*16]   (w,w) dup, [(ic*25+k)*16+oc]
//  [47392,56800)    s_p12   ull[6*14*14]   parity-split cols: idx = par*7 + c/2
//  [56800,60000)    s_feat2 ull[400]
//  [60000,60176)    s_bias2 ull[22]
#define OFF_WB1  24576
#define OFF_WB2  28192
#define OFF_P1   47392
#define OFF_FEAT 56800
#define OFF_BIAS 60000
#define SMEM_TOTAL 60192

__global__ __launch_bounds__(BDIM, 2)
void lenet_kernel(const float* __restrict__ img,
                  const float* __restrict__ train,
                  const int*   __restrict__ refs,
                  const float* __restrict__ w1, const float* __restrict__ b1,
                  const float* __restrict__ w2, const float* __restrict__ b2,
                  const float* __restrict__ Wf, const float* __restrict__ bf,
                  const float* __restrict__ Wg, const float* __restrict__ bg,
                  int n_img)
{
    extern __shared__ char smem_raw[];
    ull* s_img2  = (ull*)(smem_raw);
    ull* s_wb1   = (ull*)(smem_raw + OFF_WB1);
    ull* s_wb2   = (ull*)(smem_raw + OFF_WB2);
    ull* s_p12   = (ull*)(smem_raw + OFF_P1);
    ull* s_feat2 = (ull*)(smem_raw + OFF_FEAT);
    ull* s_bias2 = (ull*)(smem_raw + OFF_BIAS);

    const int b = blockIdx.x;
    const int t = threadIdx.x;
    const int nq2 = n_img >> 1;

    const float* srcA;
    const float* srcB;
    if (b < nq2) {
        srcA = img + (size_t)(2 * b) * 3072;
        srcB = img + (size_t)(2 * b + 1) * 3072;
    } else {
        int sA = 2 * (b - nq2);
        srcA = train + (size_t)refs[sA] * 3072;
        srcB = train + (size_t)refs[sA + 1] * 3072;
    }

    // ---- load: image pairs into parity-split layout + dup weights ----
    {
        const float4* a4 = reinterpret_cast<const float4*>(srcA);
        const float4* b4 = reinterpret_cast<const float4*>(srcB);
        for (int i = t; i < 768; i += BDIM) {
            float4 va = a4[i], vb = b4[i];
            int icy = i >> 3;        // ic*32 + y   (8 float4 per 32-col row)
            int m   = i & 7;         // cols 4m .. 4m+3
            ull* row = s_img2 + icy * 32;
            row[2 * m]          = pack2(va.x, vb.x);   // col 4m   (even -> 2m)
            row[16 + 2 * m]     = pack2(va.y, vb.y);   // col 4m+1 (odd  -> 2m)
            row[2 * m + 1]      = pack2(va.z, vb.z);   // col 4m+2 (even -> 2m+1)
            row[16 + 2 * m + 1] = pack2(va.w, vb.w);   // col 4m+3 (odd  -> 2m+1)
        }
    }
    for (int i = t; i < 450; i += BDIM) {
        int oc = i % 6, r = i / 6, k = r % 25, ic = r / 25;
        float v = w1[oc * 75 + ic * 25 + k];
        s_wb1[(ic * 25 + k) * 6 + oc] = pack2(v, v);
    }
    for (int i = t; i < 2400; i += BDIM) {
        int oc = i % 16, r = i / 16, k = r % 25, ic = r / 25;
        float v = w2[oc * 150 + ic * 25 + k];
        s_wb2[(ic * 25 + k) * 16 + oc] = pack2(v, v);
    }
    if (t < 6)       s_bias2[t] = pack2(b1[t], b1[t]);
    else if (t < 22) s_bias2[t] = pack2(b2[t - 6], b2[t - 6]);
    __syncthreads();

    // ---- conv1 + relu + maxpool2 : 6 x 14 x 14 pairs ----
    if (t < 196) {
        const int py = t / 14, px = t % 14;
        const int iy = 2 * py;

        ull a0[6], a1[6], a2[6], a3[6];
        #pragma unroll
        for (int oc = 0; oc < 6; oc++) {
            ull bz = s_bias2[oc];
            a0[oc] = bz; a1[oc] = bz; a2[oc] = bz; a3[oc] = bz;
        }
        #pragma unroll
        for (int ic = 0; ic < 3; ic++) {
            const ull* base = s_img2 + ic * 1024;
            ull rT[6], rB[6];
            {   // row iy: cols 2px+x -> even[px+x/2] / odd[px+(x-1)/2]
                const ull* row = base + iy * 32;
                rT[0] = row[px];     rT[2] = row[px + 1];     rT[4] = row[px + 2];
                rT[1] = row[16 + px]; rT[3] = row[16 + px + 1]; rT[5] = row[16 + px + 2];
            }
            #pragma unroll
            for (int ky = 0; ky < 5; ky++) {
                {
                    const ull* row = base + (iy + ky + 1) * 32;
                    rB[0] = row[px];     rB[2] = row[px + 1];     rB[4] = row[px + 2];
                    rB[1] = row[16 + px]; rB[3] = row[16 + px + 1]; rB[5] = row[16 + px + 2];
                }
                #pragma unroll
                for (int kx = 0; kx < 5; kx++) {
                    const ull* wrow = s_wb1 + (ic * 25 + ky * 5 + kx) * 6;
                    ulonglong2 w01 = *reinterpret_cast<const ulonglong2*>(wrow);
                    ulonglong2 w23 = *reinterpret_cast<const ulonglong2*>(wrow + 2);
                    ulonglong2 w45 = *reinterpret_cast<const ulonglong2*>(wrow + 4);
                    ull wv[6] = {w01.x, w01.y, w23.x, w23.y, w45.x, w45.y};
                    #pragma unroll
                    for (int oc = 0; oc < 6; oc++) {
                        a0[oc] = fma2(wv[oc], rT[kx],     a0[oc]);
                        a1[oc] = fma2(wv[oc], rT[kx + 1], a1[oc]);
                        a2[oc] = fma2(wv[oc], rB[kx],     a2[oc]);
                        a3[oc] = fma2(wv[oc], rB[kx + 1], a3[oc]);
                    }
                }
                #pragma unroll
                for (int x = 0; x < 6; x++) rT[x] = rB[x];
            }
        }
        #pragma unroll
        for (int oc = 0; oc < 6; oc++) {
            float p0, p1, q0, q1, r0, r1, s0, s1;
            unpack2(a0[oc], p0, p1);
            unpack2(a1[oc], q0, q1);
            unpack2(a2[oc], r0, r1);
            unpack2(a3[oc], s0, s1);
            float mA = fmaxf(fmaxf(p0, q0), fmaxf(r0, s0));
            float mB = fmaxf(fmaxf(p1, q1), fmaxf(r1, s1));
            // parity-split store: pooled col px -> (px&1)*7 + px/2
            s_p12[(oc * 14 + py) * 14 + (px & 1) * 7 + (px >> 1)] =
                pack2(fmaxf(mA, 0.0f), fmaxf(mB, 0.0f));
        }
    }
    __syncthreads();

    // ---- conv2 + relu + maxpool2 : 16 x 5 x 5 pairs ----
    // thread map: j = t&7 (oc pair), pos = t>>3  -> input addrs broadcast-friendly
    if (t < 200) {
        const int j   = t & 7;
        const int pos = t >> 3;
        const int py = pos / 5, px = pos % 5;
        const int iy = 2 * py;
        const int oc0 = 2 * j;

        ull aA0, aA1, aA2, aA3, aB0, aB1, aB2, aB3;
        {
            ull z0 = s_bias2[6 + oc0], z1 = s_bias2[6 + oc0 + 1];
            aA0 = z0; aA1 = z0; aA2 = z0; aA3 = z0;
            aB0 = z1; aB1 = z1; aB2 = z1; aB3 = z1;
        }
        #pragma unroll
        for (int ic = 0; ic < 6; ic++) {
            const ull* base = s_p12 + ic * 196;
            ull rT[6], rB[6];
            {
                const ull* row = base + iy * 14;
                rT[0] = row[px];     rT[2] = row[px + 1];     rT[4] = row[px + 2];
                rT[1] = row[7 + px]; rT[3] = row[7 + px + 1]; rT[5] = row[7 + px + 2];
            }
            #pragma unroll
            for (int ky = 0; ky < 5; ky++) {
                {
                    const ull* row = base + (iy + ky + 1) * 14;
                    rB[0] = row[px];     rB[2] = row[px + 1];     rB[4] = row[px + 2];
                    rB[1] = row[7 + px]; rB[3] = row[7 + px + 1]; rB[5] = row[7 + px + 2];
                }
                #pragma unroll
                for (int kx = 0; kx < 5; kx++) {
                    ulonglong2 w = *reinterpret_cast<const ulonglong2*>(
                        s_wb2 + (ic * 25 + ky * 5 + kx) * 16 + oc0);
                    aA0 = fma2(w.x, rT[kx],     aA0);
                    aA1 = fma2(w.x, rT[kx + 1], aA1);
                    aA2 = fma2(w.x, rB[kx],     aA2);
                    aA3 = fma2(w.x, rB[kx + 1], aA3);
                    aB0 = fma2(w.y, rT[kx],     aB0);
                    aB1 = fma2(w.y, rT[kx + 1], aB1);
                    aB2 = fma2(w.y, rB[kx],     aB2);
                    aB3 = fma2(w.y, rB[kx + 1], aB3);
                }
                #pragma unroll
                for (int x = 0; x < 6; x++) rT[x] = rB[x];
            }
        }
        float p0, p1, q0, q1, r0, r1, s0, s1, mA, mB;
        unpack2(aA0, p0, p1); unpack2(aA1, q0, q1);
        unpack2(aA2, r0, r1); unpack2(aA3, s0, s1);
        mA = fmaxf(fmaxf(p0, q0), fmaxf(r0, s0));
        mB = fmaxf(fmaxf(p1, q1), fmaxf(r1, s1));
        s_feat2[oc0 * 25 + pos] = pack2(fmaxf(mA, 0.0f), fmaxf(mB, 0.0f));
        unpack2(aB0, p0, p1); unpack2(aB1, q0, q1);
        unpack2(aB2, r0, r1); unpack2(aB3, s0, s1);
        mA = fmaxf(fmaxf(p0, q0), fmaxf(r0, s0));
        mB = fmaxf(fmaxf(p1, q1), fmaxf(r1, s1));
        s_feat2[(oc0 + 1) * 25 + pos] = pack2(fmaxf(mA, 0.0f), fmaxf(mB, 0.0f));
    }
    __syncthreads();

    // ---- epilogue: warp-cooperative 400-dots on feature pairs ----
    const int warp = t >> 5, lane = t & 31;
    const int nrows = (b < nq2) ? (HID * NCLS + HID) : HID;

    for (int d = warp; d < nrows; d += (BDIM >> 5)) {
        const float* wrow; float bias;
        if (b < nq2 && d < HID * NCLS) { wrow = Wg + (size_t)d * FEAT; bias = bg[d]; }
        else {
            int h = (b < nq2) ? (d - HID * NCLS) : d;
            wrow = Wf + (size_t)h * FEAT; bias = bf[h];
        }
        const float4* w4 = reinterpret_cast<const float4*>(wrow);
        ull acc = 0;
        #pragma unroll
        for (int it = 0; it < 4; it++) {
            int e4 = lane + it * 32;
            if (e4 < 100) {
                float4 w = w4[e4];
                const ull* f = s_feat2 + 4 * e4;
                acc = fma2(f[0], pack2(w.x, w.x), acc);
                acc = fma2(f[1], pack2(w.y, w.y), acc);
                acc = fma2(f[2], pack2(w.z, w.z), acc);
                acc = fma2(f[3], pack2(w.w, w.w), acc);
            }
        }
        float sA, sB;
        unpack2(acc, sA, sB);
        #pragma unroll
        for (int o = 16; o > 0; o >>= 1) {
            sA += __shfl_xor_sync(0xFFFFFFFFu, sA, o);
            sB += __shfl_xor_sync(0xFFFFFFFFu, sB, o);
        }
        if (lane == 0) {
            float vA = sA + bias, vB = sB + bias;
            if (b < nq2) {
                int qA = 2 * b, qB = 2 * b + 1;
                if (d < HID * NCLS) {
                    g_grad[(size_t)qA * (HID * NCLS) + d] = vA;
                    g_grad[(size_t)qB * (HID * NCLS) + d] = vB;
                } else {
                    g_x[(size_t)qA * HID + (d - HID * NCLS)] = vA;
                    g_x[(size_t)qB * HID + (d - HID * NCLS)] = vB;
                }
            } else {
                int sA_ = 2 * (b - nq2);
                g_rx[(size_t)sA_ * HID + d]       = vA;
                g_rx[(size_t)(sA_ + 1) * HID + d] = vB;
            }
        }
    }
}

// ---------------------------------------------------------------------------
// Head kernel: tiny combine
// ---------------------------------------------------------------------------
__global__ __launch_bounds__(128)
void head_kernel(const float* __restrict__ mem,
                 const int*   __restrict__ refs,
                 const float* __restrict__ Wm, const float* __restrict__ bm,
                 float* __restrict__ out, int n, int S)
{
    __shared__ float s_x[QPB][HID];
    __shared__ float s_g[QPB][HID * NCLS];
    __shared__ float s_diff[QPB][SMAX][HID];
    __shared__ float s_norm[QPB][SMAX];
    __shared__ float s_mem[QPB][SMAX][NCLS];
    __shared__ float s_logit[QPB][SMAX][NCLS];
    __shared__ float s_wm[NCLS * NCLS];
    __shared__ float s_bm[NCLS];
    __shared__ int   s_refs[QPB][SMAX];

    const int t = threadIdx.x;
    const int q0 = blockIdx.x * QPB;

    if (t < QPB * SMAX) {
        int ql = t / SMAX, s = t % SMAX;
        s_refs[ql][s] = refs[(size_t)(q0 + ql) * S + s];
    }
    if (t < QPB * HID) {
        int ql = t / HID, h = t % HID;
        s_x[ql][h] = g_x[(size_t)(q0 + ql) * HID + h];
    }
    for (int i = t; i < QPB * HID * NCLS; i += 128) {
        int ql = i / (HID * NCLS), d = i % (HID * NCLS);
        s_g[ql][d] = g_grad[(size_t)(q0 + ql) * (HID * NCLS) + d];
    }
    if (t < NCLS * NCLS) s_wm[t] = Wm[t];
    if (t < NCLS) s_bm[t] = bm[t];
    __syncthreads();

    for (int i = t; i < QPB * SMAX * NCLS; i += 128) {
        int ql = i / (SMAX * NCLS), r2 = i % (SMAX * NCLS);
        int s = r2 / NCLS, c = r2 % NCLS;
        s_mem[ql][s][c] = mem[(size_t)s_refs[ql][s] * NCLS + c];
    }
    if (t < QPB * SMAX) {
        int ql = t / SMAX, s = t % SMAX;
        float acc = 0.0f;
        #pragma unroll
        for (int h = 0; h < HID; h++) {
            float rx = g_rx[(size_t)((q0 + ql) * S + s) * HID + h];
            float dd = s_x[ql][h] - rx;
            s_diff[ql][s][h] = dd;
            acc += dd * dd;
        }
        s_norm[ql][s] = sqrtf(acc);
    }
    __syncthreads();

    for (int i = t; i < QPB * SMAX * NCLS; i += 128) {
        int ql = i / (SMAX * NCLS), r2 = i % (SMAX * NCLS);
        int s = r2 / NCLS, c = r2 % NCLS;
        float acc = s_bm[c];
        #pragma unroll
        for (int jj = 0; jj < NCLS; jj++)
            acc += s_wm[c * NCLS + jj] * s_mem[ql][s][jj];
        #pragma unroll
        for (int h = 0; h < HID; h++)
            acc += s_diff[ql][s][h] * s_g[ql][h * NCLS + c];
        s_logit[ql][s][c] = acc;
    }
    __syncthreads();

    if (t < QPB * NCLS) {
        int ql = t / NCLS, c = t % NCLS;
        float mx = -1e30f;
        for (int s = 0; s < S; s++) mx = fmaxf(mx, -s_norm[ql][s]);
        float se = 0.0f, acc = 0.0f;
        for (int s = 0; s < S; s++) {
            float e = expf(-s_norm[ql][s] - mx);
            se += e;
            acc += e * s_logit[ql][s][c];
        }
        out[(size_t)(q0 + ql) * NCLS + c] = acc / se;
    }
}

// ---------------------------------------------------------------------------
// launcher
// ---------------------------------------------------------------------------
extern "C" void kernel_launch(void* const* d_in, const int* in_sizes, int n_in,
                              void* d_out, int out_size)
{
    const float* img   = (const float*)d_in[0];
    const float* train = (const float*)d_in[1];
    const float* mem   = (const float*)d_in[2];
    const float* w1    = (const float*)d_in[3];
    const float* b1    = (const float*)d_in[4];
    const float* w2    = (const float*)d_in[5];
    const float* b2    = (const float*)d_in[6];
    const float* Wf    = (const float*)d_in[7];
    const float* bf    = (const float*)d_in[8];
    const float* Wg    = (const float*)d_in[9];
    const float* bg    = (const float*)d_in[10];
    const float* Wm    = (const float*)d_in[11];
    const float* bm    = (const float*)d_in[12];
    // d_in[13] = idx : unused
    const int*   refs  = (const int*)d_in[14];

    const int n = in_sizes[0] / (3 * 32 * 32);   // 1024
    const int S = in_sizes[14] / n;              // 8
    if (n > NQ_MAX || S != SMAX || (n % QPB) != 0 || (n % 2) != 0) return;

    cudaFuncSetAttribute(lenet_kernel,
                         cudaFuncAttributeMaxDynamicSharedMemorySize, SMEM_TOTAL);

    const int nblocks = (n + n * S) / 2;         // 4608 image-pair blocks
    lenet_kernel<<<nblocks, BDIM, SMEM_TOTAL>>>(img, train, refs,
                                                w1, b1, w2, b2,
                                                Wf, bf, Wg, bg, n);
    head_kernel<<<n / QPB, 128>>>(mem, refs, Wm, bm, (float*)d_out, n, S);
}